// round 4
// baseline (speedup 1.0000x reference)
#include <cuda_runtime.h>
#include <math.h>

#define Bz  64
#define Sz  512
#define INz 512
#define Hz  1024
#define G3z 3072
#define NBLK 128

// ---------------- scratch (device globals; no allocation allowed) ----------------
__device__ float g_gi0[(size_t)2 * Bz * Sz * G3z];   // [dir][b][s][n]
__device__ float g_gi1[(size_t)2 * Sz * Bz * G3z];   // [dir][s][b][n]
__device__ float g_h0 [(size_t)2 * Sz * Bz * Hz];    // [dir][s][b][j]
__device__ float g_h1 [(size_t)2 * 2 * Bz * Hz];     // ping-pong [buf][dir][b][j]
__device__ float g_W0 [(size_t)2 * G3z * INz];       // packed w_ih0f + feature-reversed w_ih0b
__device__ float g_b0 [2 * G3z];
__device__ unsigned g_count;
__device__ unsigned g_phase;

// ---------------- grid barrier (release/acquire, monotonic phase) -----------------
__device__ __forceinline__ void grid_barrier(unsigned target)
{
    __syncthreads();
    if (threadIdx.x == 0) {
        unsigned old;
        asm volatile("atom.release.gpu.add.u32 %0, [%1], 1;"
                     : "=r"(old) : "l"(&g_count) : "memory");
        if (old == NBLK - 1) {
            g_count = 0;
            asm volatile("red.release.gpu.add.u32 [%0], 1;"
                         :: "l"(&g_phase) : "memory");
        } else {
            unsigned v;
            do {
                asm volatile("ld.acquire.gpu.u32 %0, [%1];"
                             : "=r"(v) : "l"(&g_phase) : "memory");
            } while (v < target);
        }
    }
    __syncthreads();
}

// ---------------- prep: pack layer0 input weights (dir1 feature-reversed) --------
__global__ void prep_kernel(const float* __restrict__ wf, const float* __restrict__ wb,
                            const float* __restrict__ bf, const float* __restrict__ bb)
{
    size_t i = (size_t)blockIdx.x * 256 + threadIdx.x;
    size_t total = (size_t)G3z * INz;
    if (i == 0) { g_count = 0; g_phase = 0; }
    if (i < total) {
        size_t n = i / INz, k = i % INz;
        g_W0[i]         = wf[i];
        g_W0[total + i] = wb[n * INz + (INz - 1 - k)];
    }
    if (i < G3z) {
        g_b0[i]        = bf[i];
        g_b0[G3z + i]  = bb[i];
    }
}

// ---------------- big GEMM: C[m, n] = sum_k A[m,k] * W[n,k] + bias[n] -------------
#define BM 128
#define BN 128
#define BK 16

__global__ void __launch_bounds__(256) gemm_nt_bias(
    const float* __restrict__ A, int lda,
    const float* __restrict__ W, int ldw,
    const float* __restrict__ bias,
    float* __restrict__ C,
    int M, int N, int K, size_t dirStride, int N0)
{
    __shared__ float As[BK][BM];
    __shared__ float Bs[BK][BN];

    int bn = blockIdx.x, bm = blockIdx.y;
    int tid = threadIdx.x;
    int tr = tid / 16, tc = tid % 16;

    const float* Ab = A + (size_t)bm * BM * lda;
    const float* Wb = W + (size_t)bn * BN * ldw;

    float acc[8][8];
#pragma unroll
    for (int i = 0; i < 8; i++)
#pragma unroll
        for (int j = 0; j < 8; j++) acc[i][j] = 0.f;

    for (int kt = 0; kt < K; kt += BK) {
#pragma unroll
        for (int i = 0; i < 2; i++) {
            int f = tid * 2 + i;           // 0..511
            int row = f >> 2;
            int kq  = (f & 3) * 4;
            float4 va = *(const float4*)(Ab + (size_t)row * lda + kt + kq);
            As[kq + 0][row] = va.x; As[kq + 1][row] = va.y;
            As[kq + 2][row] = va.z; As[kq + 3][row] = va.w;
            float4 vb = *(const float4*)(Wb + (size_t)row * ldw + kt + kq);
            Bs[kq + 0][row] = vb.x; Bs[kq + 1][row] = vb.y;
            Bs[kq + 2][row] = vb.z; Bs[kq + 3][row] = vb.w;
        }
        __syncthreads();
#pragma unroll
        for (int k = 0; k < BK; k++) {
            float a[8], b[8];
            *(float4*)&a[0] = *(const float4*)&As[k][tr * 8];
            *(float4*)&a[4] = *(const float4*)&As[k][tr * 8 + 4];
            *(float4*)&b[0] = *(const float4*)&Bs[k][tc * 8];
            *(float4*)&b[4] = *(const float4*)&Bs[k][tc * 8 + 4];
#pragma unroll
            for (int i = 0; i < 8; i++)
#pragma unroll
                for (int j = 0; j < 8; j++) acc[i][j] += a[i] * b[j];
        }
        __syncthreads();
    }

#pragma unroll
    for (int i = 0; i < 8; i++) {
        size_t m = (size_t)bm * BM + tr * 8 + i;
#pragma unroll
        for (int j = 0; j < 8; j++) {
            int n = bn * BN + tc * 8 + j;
            float v = acc[i][j] + __ldg(&bias[n]);
            int dir = n / N0;
            int nn  = n - dir * N0;
            C[(size_t)dir * dirStride + m * G3z + nn] = v;
        }
    }
}

// ---------------- persistent recurrent layer: 512 steps in one kernel -------------
// grid = 128 CTAs: d = bx>>6 (direction), jg = bx&63 (16-column group of H).
// CTA's W_hh slice (48 x 1024) lives in smem for the whole kernel.
// smem: sh_w[48*1024] + sh_x[3136] (h tile 64x36 / gate exchange 48x65)
#define SH_W_FLOATS (48 * 1024)
#define SH_X_FLOATS 3136
#define SMEM_BYTES ((SH_W_FLOATS + SH_X_FLOATS) * 4)

__global__ void __launch_bounds__(256) gru_layer_persistent(
    const float* __restrict__ gi_base, size_t gi_dstride, size_t gi_tstride, size_t gi_bstride,
    const float* __restrict__ whf, const float* __restrict__ whb,
    const float* __restrict__ bhf, const float* __restrict__ bhb,
    float* __restrict__ hbuf,
    int mode,                 // 0: store h for every t (layer0), 1: ping-pong + dout (layer1)
    unsigned phase_base,
    float* __restrict__ dout)
{
    extern __shared__ float smem[];
    float* sh_w = smem;
    float* sh_x = smem + SH_W_FLOATS;

    int d  = blockIdx.x >> 6;
    int jg = blockIdx.x & 63;
    int tid = threadIdx.x;
    int q = tid >> 6;   // 0..3 -> owns 12 of the 48 gate-columns
    int r = tid & 63;   // batch row

    const float* w  = d ? whb : whf;
    const float* bh = d ? bhb : bhf;

    // one-time: load this CTA's weight slice into smem (48 gate-rows x 1024 k)
    for (int f = tid; f < 48 * 256; f += 256) {
        int row = f >> 8;            // 0..47
        int k4  = (f & 255) * 4;     // 0..1020
        int wrow = (row >> 4) * Hz + jg * 16 + (row & 15);
        *(float4*)&sh_w[row * 1024 + k4] = *(const float4*)(w + (size_t)wrow * Hz + k4);
    }
    float bias[12];
#pragma unroll
    for (int c = 0; c < 12; c++) {
        int cg = q * 12 + c;
        bias[c] = __ldg(&bh[(cg >> 4) * Hz + jg * 16 + (cg & 15)]);
    }
    __syncthreads();

    int jj = tid & 15;
    int rb = tid >> 4;
    int jglob = jg * 16 + jj;

    for (int t = 0; t < Sz; t++) {
        if (t > 0) grid_barrier(phase_base + (unsigned)t);

        const float* hp;
        float* ho;
        if (mode == 0) {
            hp = hbuf + ((size_t)d * Sz + (size_t)(t > 0 ? t - 1 : 0)) * Bz * Hz;
            ho = hbuf + ((size_t)d * Sz + t) * Bz * Hz;
        } else {
            int cur = t & 1;
            hp = hbuf + ((size_t)cur * 2 + d) * Bz * Hz;
            ho = hbuf + ((size_t)(cur ^ 1) * 2 + d) * Bz * Hz;
        }
        const float* gi = gi_base + (size_t)d * gi_dstride + (size_t)t * gi_tstride;

        float acc[12];
#pragma unroll
        for (int c = 0; c < 12; c++) acc[c] = 0.f;

        if (t > 0) {
            for (int kt = 0; kt < Hz; kt += 32) {
                // h_prev tile: 64 rows x 32 k into sh_x (stride 36)
#pragma unroll
                for (int i = 0; i < 2; i++) {
                    int f = tid * 2 + i;
                    int row = f >> 3;
                    int kq  = (f & 7) * 4;
                    *(float4*)&sh_x[row * 36 + kq] =
                        *(const float4*)(hp + (size_t)row * Hz + kt + kq);
                }
                __syncthreads();
#pragma unroll
                for (int k4 = 0; k4 < 32; k4 += 4) {
                    float4 hv = *(const float4*)&sh_x[r * 36 + k4];
#pragma unroll
                    for (int c = 0; c < 12; c++) {
                        float4 wv = *(const float4*)&sh_w[(q * 12 + c) * 1024 + kt + k4];
                        acc[c] += hv.x * wv.x;
                        acc[c] += hv.y * wv.y;
                        acc[c] += hv.z * wv.z;
                        acc[c] += hv.w * wv.w;
                    }
                }
                __syncthreads();
            }
        }

#pragma unroll
        for (int c = 0; c < 12; c++) acc[c] += bias[c];

        // exchange so each thread gets full (r,z,n) triples
#pragma unroll
        for (int c = 0; c < 12; c++) sh_x[(q * 12 + c) * 65 + r] = acc[c];
        __syncthreads();

#pragma unroll
        for (int i = 0; i < 4; i++) {
            int row = rb + 16 * i;  // batch index
            float ghr = sh_x[(jj)      * 65 + row];
            float ghz = sh_x[(16 + jj) * 65 + row];
            float ghn = sh_x[(32 + jj) * 65 + row];
            size_t gbase = (size_t)row * gi_bstride + jglob;
            float gir = gi[gbase];
            float giz = gi[gbase + Hz];
            float gin = gi[gbase + 2 * Hz];
            float hpv = (t > 0) ? hp[(size_t)row * Hz + jglob] : 0.f;

            float rg = 1.f / (1.f + expf(-(gir + ghr)));
            float zg = 1.f / (1.f + expf(-(giz + ghz)));
            float ng = tanhf(gin + rg * ghn);
            float hnew = (1.f - zg) * ng + zg * hpv;

            ho[(size_t)row * Hz + jglob] = hnew;
            if (mode == 1) {
                dout[((size_t)row * Sz + t) * 2048 + (size_t)d * Hz + jglob] = hnew;
                if (t == Sz - 1)
                    dout[(size_t)Bz * Sz * 2048 + (size_t)row * 2048 + (size_t)d * Hz + jglob] = hnew;
            }
        }
        __syncthreads();   // protect sh_x before next step's h-tile loads
    }
}

// ---------------- host launcher (graph-capturable: 6 kernel nodes) ----------------
extern "C" void kernel_launch(void* const* d_in, const int* in_sizes, int n_in,
                              void* d_out, int out_size)
{
    const float* x      = (const float*)d_in[0];
    const float* w_hh0f = (const float*)d_in[2];
    const float* b_hh0f = (const float*)d_in[4];
    const float* w_hh0b = (const float*)d_in[6];
    const float* b_hh0b = (const float*)d_in[8];
    const float* w_ih1f = (const float*)d_in[9];
    const float* w_hh1f = (const float*)d_in[10];
    const float* b_ih1f = (const float*)d_in[11];
    const float* b_hh1f = (const float*)d_in[12];
    const float* w_ih1b = (const float*)d_in[13];
    const float* w_hh1b = (const float*)d_in[14];
    const float* b_ih1b = (const float*)d_in[15];
    const float* b_hh1b = (const float*)d_in[16];
    float* out = (float*)d_out;

    float *gi0, *gi1, *h0, *h1, *W0, *b0;
    cudaGetSymbolAddress((void**)&gi0, g_gi0);
    cudaGetSymbolAddress((void**)&gi1, g_gi1);
    cudaGetSymbolAddress((void**)&h0,  g_h0);
    cudaGetSymbolAddress((void**)&h1,  g_h1);
    cudaGetSymbolAddress((void**)&W0,  g_W0);
    cudaGetSymbolAddress((void**)&b0,  g_b0);

    cudaFuncSetAttribute(gru_layer_persistent,
                         cudaFuncAttributeMaxDynamicSharedMemorySize, SMEM_BYTES);

    // 1) pack layer0 input weights + reset barrier state
    prep_kernel<<<(G3z * INz + 255) / 256, 256>>>(
        (const float*)d_in[1], (const float*)d_in[5],
        (const float*)d_in[3], (const float*)d_in[7]);

    // 2) gi0 = x @ [W_ih0f ; rev(W_ih0b)]^T + bias  (both dirs in one GEMM)
    gemm_nt_bias<<<dim3((2 * G3z) / BN, (Bz * Sz) / BM), 256>>>(
        x, INz, W0, INz, b0, gi0,
        Bz * Sz, 2 * G3z, INz, (size_t)Bz * Sz * G3z, G3z);

    // 3) layer-0 recurrence, one persistent kernel (phases 1..511)
    gru_layer_persistent<<<NBLK, 256, SMEM_BYTES>>>(
        gi0, (size_t)Bz * Sz * G3z, (size_t)G3z, (size_t)Sz * G3z,
        w_hh0f, w_hh0b, b_hh0f, b_hh0b,
        h0, 0, 0u, nullptr);

    // 4) gi1 = h0_all @ W_ih1^T + bias (per direction, parallel over time)
    for (int dir = 0; dir < 2; dir++) {
        gemm_nt_bias<<<dim3(G3z / BN, (Sz * Bz) / BM), 256>>>(
            h0 + (size_t)dir * Sz * Bz * Hz, Hz,
            dir ? w_ih1b : w_ih1f, Hz,
            dir ? b_ih1b : b_ih1f,
            gi1 + (size_t)dir * Sz * Bz * G3z,
            Sz * Bz, G3z, Hz, (size_t)0, G3z);
    }

    // 5) layer-1 recurrence, one persistent kernel (phases 512..1022)
    gru_layer_persistent<<<NBLK, 256, SMEM_BYTES>>>(
        gi1, (size_t)Sz * Bz * G3z, (size_t)Bz * G3z, (size_t)G3z,
        w_hh1f, w_hh1b, b_hh1f, b_hh1b,
        h1, 1, (unsigned)(Sz - 1), out);
}

// round 6
// speedup vs baseline: 1.1056x; 1.1056x over previous
#include <cuda_runtime.h>
#include <cuda_bf16.h>
#include <math.h>
#include <stdint.h>

#define Bz  64
#define Sz  512
#define INz 512
#define Hz  1024
#define G3z 3072
#define NBLK 128

// ---------------- scratch (device globals; no allocation allowed) ----------------
__device__ float g_gi0[(size_t)2 * Bz * Sz * G3z];   // [dir][b][s][n]
__device__ float g_gi1[(size_t)2 * Sz * Bz * G3z];   // [dir][s][b][n]
__device__ float g_h0 [(size_t)2 * Sz * Bz * Hz];    // [dir][s][b][j]
__device__ float g_h1 [(size_t)2 * 2 * Bz * Hz];     // ping-pong [buf][dir][b][j]
__device__ float g_W0 [(size_t)2 * G3z * INz];       // packed w_ih0f + feature-reversed w_ih0b
__device__ float g_b0 [2 * G3z];
__device__ unsigned g_count;
__device__ unsigned g_phase;

__device__ __forceinline__ uint32_t smem_u32(const void* p) {
    uint32_t a;
    asm("{ .reg .u64 t; cvta.to.shared.u64 t, %1; cvt.u32.u64 %0, t; }" : "=r"(a) : "l"(p));
    return a;
}

// ---------------- grid barrier (release/acquire, monotonic phase) -----------------
__device__ __forceinline__ void grid_barrier(unsigned target)
{
    __syncthreads();
    if (threadIdx.x == 0) {
        unsigned old;
        asm volatile("atom.release.gpu.add.u32 %0, [%1], 1;"
                     : "=r"(old) : "l"(&g_count) : "memory");
        if (old == NBLK - 1) {
            g_count = 0;
            asm volatile("red.release.gpu.add.u32 [%0], 1;"
                         :: "l"(&g_phase) : "memory");
        } else {
            unsigned v;
            do {
                asm volatile("ld.acquire.gpu.u32 %0, [%1];"
                             : "=r"(v) : "l"(&g_phase) : "memory");
            } while (v < target);
        }
    }
    __syncthreads();
}

// ---------------- prep: pack layer0 input weights (dir1 feature-reversed) --------
__global__ void prep_kernel(const float* __restrict__ wf, const float* __restrict__ wb,
                            const float* __restrict__ bf, const float* __restrict__ bb)
{
    size_t i = (size_t)blockIdx.x * 256 + threadIdx.x;
    size_t total = (size_t)G3z * INz;
    if (i == 0) { g_count = 0; g_phase = 0; }
    if (i < total) {
        size_t n = i / INz, k = i % INz;
        g_W0[i]         = wf[i];
        g_W0[total + i] = wb[n * INz + (INz - 1 - k)];
    }
    if (i < G3z) {
        g_b0[i]        = bf[i];
        g_b0[G3z + i]  = bb[i];
    }
}

// ================ HMMA split-bf16 GEMM: C = A @ W^T + bias ================
// mma.sync.m16n8k16 bf16 (sm_80 base feature -> works at compute_103).
// fp32 -> (hi,lo) bf16; D += Ahi*Bhi + Ahi*Blo + Alo*Bhi (fp32 accum).
// 128x128 tile, K-chunk 32, double-buffered smem, 8 warps = 2(m) x 4(n).
#define LDSTR 40                    // bf16 per smem row (32 + 8 pad)
#define TILE_ELEMS (128 * LDSTR)    // 5120 bf16 per operand tile
#define BUF_ELEMS  (4 * TILE_ELEMS) // Ahi, Alo, Bhi, Blo
#define GEMM_SMEM_BYTES (2 * BUF_ELEMS * 2)   // 81920

__device__ __forceinline__ void f8_to_hilo(float4 u, float4 v, uint4& h, uint4& l)
{
    __nv_bfloat162 h0 = __floats2bfloat162_rn(u.x, u.y);
    __nv_bfloat162 h1 = __floats2bfloat162_rn(u.z, u.w);
    __nv_bfloat162 h2 = __floats2bfloat162_rn(v.x, v.y);
    __nv_bfloat162 h3 = __floats2bfloat162_rn(v.z, v.w);
    float2 f0 = __bfloat1622float2(h0), f1 = __bfloat1622float2(h1);
    float2 f2 = __bfloat1622float2(h2), f3 = __bfloat1622float2(h3);
    __nv_bfloat162 l0 = __floats2bfloat162_rn(u.x - f0.x, u.y - f0.y);
    __nv_bfloat162 l1 = __floats2bfloat162_rn(u.z - f1.x, u.w - f1.y);
    __nv_bfloat162 l2 = __floats2bfloat162_rn(v.x - f2.x, v.y - f2.y);
    __nv_bfloat162 l3 = __floats2bfloat162_rn(v.z - f3.x, v.w - f3.y);
    h = make_uint4(*(uint32_t*)&h0, *(uint32_t*)&h1, *(uint32_t*)&h2, *(uint32_t*)&h3);
    l = make_uint4(*(uint32_t*)&l0, *(uint32_t*)&l1, *(uint32_t*)&l2, *(uint32_t*)&l3);
}

__device__ __forceinline__ void ldm_x4(uint32_t* r, uint32_t addr) {
    asm volatile("ldmatrix.sync.aligned.m8n8.x4.shared.b16 {%0,%1,%2,%3}, [%4];"
                 : "=r"(r[0]), "=r"(r[1]), "=r"(r[2]), "=r"(r[3]) : "r"(addr));
}

__device__ __forceinline__ void mma_16816(float* c, const uint32_t* a, const uint32_t* b) {
    asm volatile(
        "mma.sync.aligned.m16n8k16.row.col.f32.bf16.bf16.f32 "
        "{%0,%1,%2,%3}, {%4,%5,%6,%7}, {%8,%9}, {%0,%1,%2,%3};"
        : "+f"(c[0]), "+f"(c[1]), "+f"(c[2]), "+f"(c[3])
        : "r"(a[0]), "r"(a[1]), "r"(a[2]), "r"(a[3]), "r"(b[0]), "r"(b[1]));
}

__global__ void __launch_bounds__(256) gemm_hmma(
    const float* __restrict__ A, int lda,
    const float* __restrict__ W, int ldw,
    const float* __restrict__ bias,
    float* __restrict__ C,
    int K, size_t dirStride, int N0)
{
    extern __shared__ __nv_bfloat16 sm[];
    const int tid = threadIdx.x, lane = tid & 31, wid = tid >> 5;
    const int wm = wid >> 2, wn = wid & 3;
    const int bn = blockIdx.x, bm = blockIdx.y;

    const float* Ab = A + (size_t)bm * 128 * lda;
    const float* Wb = W + (size_t)bn * 128 * ldw;

    const int lrow = tid >> 1;
    const int lks  = (tid & 1) * 16;

    float acc[4][4][4];
#pragma unroll
    for (int mi = 0; mi < 4; mi++)
#pragma unroll
        for (int ni = 0; ni < 4; ni++)
#pragma unroll
            for (int e = 0; e < 4; e++) acc[mi][ni][e] = 0.f;

    float4 ra[4], rb[4];
    const int NC = K / 32;
    const uint32_t smb = smem_u32(sm);

    // precomputed per-thread smem byte addrs (relative, add buf/operand/k16)
    const uint32_t a_rowoff = (uint32_t)((wm * 64 + (lane & 15)) * LDSTR + (lane >> 4) * 8) * 2;
    const uint32_t b_rowoff = (uint32_t)((wn * 32 + (lane & 7) + ((lane >> 4) & 1) * 8) * LDSTR
                                         + ((lane >> 3) & 1) * 8) * 2;

#define LDG_CHUNK(c) do {                                                     \
        int kt = (c) * 32 + lks;                                              \
        const float* pa = Ab + (size_t)lrow * lda + kt;                       \
        const float* pw = Wb + (size_t)lrow * ldw + kt;                       \
        ra[0] = *(const float4*)(pa);      ra[1] = *(const float4*)(pa + 4);  \
        ra[2] = *(const float4*)(pa + 8);  ra[3] = *(const float4*)(pa + 12); \
        rb[0] = *(const float4*)(pw);      rb[1] = *(const float4*)(pw + 4);  \
        rb[2] = *(const float4*)(pw + 8);  rb[3] = *(const float4*)(pw + 12); \
    } while (0)

#define STS_CHUNK(buf) do {                                                   \
        __nv_bfloat16* base = sm + (buf) * BUF_ELEMS + lrow * LDSTR + lks;    \
        uint4 h, l;                                                           \
        f8_to_hilo(ra[0], ra[1], h, l);                                       \
        *(uint4*)(base)                  = h;                                 \
        *(uint4*)(base + TILE_ELEMS)     = l;                                 \
        f8_to_hilo(ra[2], ra[3], h, l);                                       \
        *(uint4*)(base + 8)              = h;                                 \
        *(uint4*)(base + TILE_ELEMS + 8) = l;                                 \
        f8_to_hilo(rb[0], rb[1], h, l);                                       \
        *(uint4*)(base + 2 * TILE_ELEMS)     = h;                             \
        *(uint4*)(base + 3 * TILE_ELEMS)     = l;                             \
        f8_to_hilo(rb[2], rb[3], h, l);                                       \
        *(uint4*)(base + 2 * TILE_ELEMS + 8) = h;                             \
        *(uint4*)(base + 3 * TILE_ELEMS + 8) = l;                             \
    } while (0)

    LDG_CHUNK(0);
    STS_CHUNK(0);
    __syncthreads();

    for (int c = 0; c < NC; c++) {
        const int buf = c & 1;
        if (c + 1 < NC) LDG_CHUNK(c + 1);

        const uint32_t bufb = smb + (uint32_t)buf * (BUF_ELEMS * 2);
        // passes: (Ahi,Bhi), (Ahi,Blo), (Alo,Bhi)  — offsets in bytes
        const uint32_t aoffs[3] = { 0u, 0u, (uint32_t)TILE_ELEMS * 2 };
        const uint32_t boffs[3] = { (uint32_t)2 * TILE_ELEMS * 2,
                                    (uint32_t)3 * TILE_ELEMS * 2,
                                    (uint32_t)2 * TILE_ELEMS * 2 };
#pragma unroll
        for (int p = 0; p < 3; p++) {
#pragma unroll
            for (int k16 = 0; k16 < 32; k16 += 16) {
                uint32_t af[4][4], bf[2][4];
#pragma unroll
                for (int mi = 0; mi < 4; mi++)
                    ldm_x4(af[mi], bufb + aoffs[p] + a_rowoff
                                   + (uint32_t)(mi * 16 * LDSTR + k16) * 2);
#pragma unroll
                for (int nj = 0; nj < 2; nj++)
                    ldm_x4(bf[nj], bufb + boffs[p] + b_rowoff
                                   + (uint32_t)(nj * 16 * LDSTR + k16) * 2);
#pragma unroll
                for (int mi = 0; mi < 4; mi++)
#pragma unroll
                    for (int ni = 0; ni < 4; ni++)
                        mma_16816(acc[mi][ni], af[mi], &bf[ni >> 1][(ni & 1) * 2]);
            }
        }

        if (c + 1 < NC) STS_CHUNK((c + 1) & 1);
        __syncthreads();
    }

    // epilogue: add bias, scatter to packed-dir layout
    const int grow = lane >> 2;
    const int gcol = (lane & 3) * 2;
    const int nbase = bn * 128;
    const int dir = nbase / N0;
    const int nn_base = nbase - dir * N0;
    float* Cd = C + (size_t)dir * dirStride;

#pragma unroll
    for (int mi = 0; mi < 4; mi++) {
        size_t m0 = (size_t)bm * 128 + wm * 64 + mi * 16 + grow;
#pragma unroll
        for (int ni = 0; ni < 4; ni++) {
            int nloc = wn * 32 + ni * 8 + gcol;
            float bx = __ldg(&bias[nbase + nloc]);
            float by = __ldg(&bias[nbase + nloc + 1]);
            float2 v0 = make_float2(acc[mi][ni][0] + bx, acc[mi][ni][1] + by);
            float2 v1 = make_float2(acc[mi][ni][2] + bx, acc[mi][ni][3] + by);
            *(float2*)(Cd + m0 * G3z + nn_base + nloc)       = v0;
            *(float2*)(Cd + (m0 + 8) * G3z + nn_base + nloc) = v1;
        }
    }
#undef LDG_CHUNK
#undef STS_CHUNK
}

// ---------------- persistent recurrent layer: 512 steps in one kernel -------------
#define SH_W_FLOATS (48 * 1024)
#define SH_X_FLOATS 3136
#define SMEM_BYTES ((SH_W_FLOATS + SH_X_FLOATS) * 4)

__global__ void __launch_bounds__(256) gru_layer_persistent(
    const float* __restrict__ gi_base, size_t gi_dstride, size_t gi_tstride, size_t gi_bstride,
    const float* __restrict__ whf, const float* __restrict__ whb,
    const float* __restrict__ bhf, const float* __restrict__ bhb,
    float* __restrict__ hbuf,
    int mode, unsigned phase_base, float* __restrict__ dout)
{
    extern __shared__ float smemf[];
    float* sh_w = smemf;
    float* sh_x = smemf + SH_W_FLOATS;

    int d  = blockIdx.x >> 6;
    int jg = blockIdx.x & 63;
    int tid = threadIdx.x;
    int q = tid >> 6;
    int r = tid & 63;

    const float* w  = d ? whb : whf;
    const float* bh = d ? bhb : bhf;

    for (int f = tid; f < 48 * 256; f += 256) {
        int row = f >> 8;
        int k4  = (f & 255) * 4;
        int wrow = (row >> 4) * Hz + jg * 16 + (row & 15);
        *(float4*)&sh_w[row * 1024 + k4] = *(const float4*)(w + (size_t)wrow * Hz + k4);
    }
    float bias[12];
#pragma unroll
    for (int c = 0; c < 12; c++) {
        int cg = q * 12 + c;
        bias[c] = __ldg(&bh[(cg >> 4) * Hz + jg * 16 + (cg & 15)]);
    }
    __syncthreads();

    int jj = tid & 15;
    int rb = tid >> 4;
    int jglob = jg * 16 + jj;

    for (int t = 0; t < Sz; t++) {
        if (t > 0) grid_barrier(phase_base + (unsigned)t);

        const float* hp;
        float* ho;
        if (mode == 0) {
            hp = hbuf + ((size_t)d * Sz + (size_t)(t > 0 ? t - 1 : 0)) * Bz * Hz;
            ho = hbuf + ((size_t)d * Sz + t) * Bz * Hz;
        } else {
            int cur = t & 1;
            hp = hbuf + ((size_t)cur * 2 + d) * Bz * Hz;
            ho = hbuf + ((size_t)(cur ^ 1) * 2 + d) * Bz * Hz;
        }
        const float* gi = gi_base + (size_t)d * gi_dstride + (size_t)t * gi_tstride;

        float acc[12];
#pragma unroll
        for (int c = 0; c < 12; c++) acc[c] = 0.f;

        if (t > 0) {
            for (int kt = 0; kt < Hz; kt += 32) {
#pragma unroll
                for (int i = 0; i < 2; i++) {
                    int f = tid * 2 + i;
                    int row = f >> 3;
                    int kq  = (f & 7) * 4;
                    *(float4*)&sh_x[row * 36 + kq] =
                        *(const float4*)(hp + (size_t)row * Hz + kt + kq);
                }
                __syncthreads();
#pragma unroll
                for (int k4 = 0; k4 < 32; k4 += 4) {
                    float4 hv = *(const float4*)&sh_x[r * 36 + k4];
#pragma unroll
                    for (int c = 0; c < 12; c++) {
                        float4 wv = *(const float4*)&sh_w[(q * 12 + c) * 1024 + kt + k4];
                        acc[c] += hv.x * wv.x;
                        acc[c] += hv.y * wv.y;
                        acc[c] += hv.z * wv.z;
                        acc[c] += hv.w * wv.w;
                    }
                }
                __syncthreads();
            }
        }

#pragma unroll
        for (int c = 0; c < 12; c++) acc[c] += bias[c];

#pragma unroll
        for (int c = 0; c < 12; c++) sh_x[(q * 12 + c) * 65 + r] = acc[c];
        __syncthreads();

#pragma unroll
        for (int i = 0; i < 4; i++) {
            int row = rb + 16 * i;
            float ghr = sh_x[(jj)      * 65 + row];
            float ghz = sh_x[(16 + jj) * 65 + row];
            float ghn = sh_x[(32 + jj) * 65 + row];
            size_t gbase = (size_t)row * gi_bstride + jglob;
            float gir = gi[gbase];
            float giz = gi[gbase + Hz];
            float gin = gi[gbase + 2 * Hz];
            float hpv = (t > 0) ? hp[(size_t)row * Hz + jglob] : 0.f;

            float rg = 1.f / (1.f + expf(-(gir + ghr)));
            float zg = 1.f / (1.f + expf(-(giz + ghz)));
            float ng = tanhf(gin + rg * ghn);
            float hnew = (1.f - zg) * ng + zg * hpv;

            ho[(size_t)row * Hz + jglob] = hnew;
            if (mode == 1) {
                dout[((size_t)row * Sz + t) * 2048 + (size_t)d * Hz + jglob] = hnew;
                if (t == Sz - 1)
                    dout[(size_t)Bz * Sz * 2048 + (size_t)row * 2048 + (size_t)d * Hz + jglob] = hnew;
            }
        }
        __syncthreads();
    }
}

// ---------------- host launcher (graph-capturable: 6 kernel nodes) ----------------
extern "C" void kernel_launch(void* const* d_in, const int* in_sizes, int n_in,
                              void* d_out, int out_size)
{
    const float* x      = (const float*)d_in[0];
    const float* w_hh0f = (const float*)d_in[2];
    const float* b_hh0f = (const float*)d_in[4];
    const float* w_hh0b = (const float*)d_in[6];
    const float* b_hh0b = (const float*)d_in[8];
    const float* w_ih1f = (const float*)d_in[9];
    const float* w_hh1f = (const float*)d_in[10];
    const float* b_ih1f = (const float*)d_in[11];
    const float* b_hh1f = (const float*)d_in[12];
    const float* w_ih1b = (const float*)d_in[13];
    const float* w_hh1b = (const float*)d_in[14];
    const float* b_ih1b = (const float*)d_in[15];
    const float* b_hh1b = (const float*)d_in[16];
    float* out = (float*)d_out;

    float *gi0, *gi1, *h0, *h1, *W0, *b0;
    cudaGetSymbolAddress((void**)&gi0, g_gi0);
    cudaGetSymbolAddress((void**)&gi1, g_gi1);
    cudaGetSymbolAddress((void**)&h0,  g_h0);
    cudaGetSymbolAddress((void**)&h1,  g_h1);
    cudaGetSymbolAddress((void**)&W0,  g_W0);
    cudaGetSymbolAddress((void**)&b0,  g_b0);

    cudaFuncSetAttribute(gru_layer_persistent,
                         cudaFuncAttributeMaxDynamicSharedMemorySize, SMEM_BYTES);
    cudaFuncSetAttribute(gemm_hmma,
                         cudaFuncAttributeMaxDynamicSharedMemorySize, GEMM_SMEM_BYTES);

    // 1) pack layer0 input weights + reset barrier state
    prep_kernel<<<(G3z * INz + 255) / 256, 256>>>(
        (const float*)d_in[1], (const float*)d_in[5],
        (const float*)d_in[3], (const float*)d_in[7]);

    // 2) gi0 = x @ [W_ih0f ; rev(W_ih0b)]^T + bias  (HMMA split-bf16)
    gemm_hmma<<<dim3((2 * G3z) / 128, (Bz * Sz) / 128), 256, GEMM_SMEM_BYTES>>>(
        x, INz, W0, INz, b0, gi0,
        INz, (size_t)Bz * Sz * G3z, G3z);

    // 3) layer-0 recurrence, one persistent kernel (phases 1..511)
    gru_layer_persistent<<<NBLK, 256, SMEM_BYTES>>>(
        gi0, (size_t)Bz * Sz * G3z, (size_t)G3z, (size_t)Sz * G3z,
        w_hh0f, w_hh0b, b_hh0f, b_hh0b,
        h0, 0, 0u, nullptr);

    // 4) gi1 = h0_all @ W_ih1^T + bias (HMMA split-bf16, per dir)
    for (int dir = 0; dir < 2; dir++) {
        gemm_hmma<<<dim3(G3z / 128, (Sz * Bz) / 128), 256, GEMM_SMEM_BYTES>>>(
            h0 + (size_t)dir * Sz * Bz * Hz, Hz,
            dir ? w_ih1b : w_ih1f, Hz,
            dir ? b_ih1b : b_ih1f,
            gi1 + (size_t)dir * Sz * Bz * G3z,
            Hz, (size_t)0, G3z);
    }

    // 5) layer-1 recurrence, one persistent kernel (phases 512..1022)
    gru_layer_persistent<<<NBLK, 256, SMEM_BYTES>>>(
        gi1, (size_t)Sz * Bz * G3z, (size_t)Bz * G3z, (size_t)G3z,
        w_hh1f, w_hh1b, b_hh1f, b_hh1b,
        h1, 1, (unsigned)(Sz - 1), out);
}